// round 7
// baseline (speedup 1.0000x reference)
#include <cuda_runtime.h>

// Ricker scan, chunk-parallel via contraction warm-up (round 7: cubic chain).
//   n_{i+1} = n_i * exp(alpha*(1 - beta*n_i + f_i)) + sigma*eps_i
// Deg-2 exp Taylor collected as a cubic in n:
//   n' = K2*n^3 + K1*n^2 + K0*n + e,
//   K0 = 1+a+a^2/2, K1 = -c(1+a), K2 = c^2/2 (const), a = alpha*(1+f), c = alpha*beta
// Chain: {t1=fma(K2,n,K1), n2=n*n, u=fma(K0,n,e)} -> n'=fma(t1,n2,u): 8 cyc/step.
// K0,K1,e precomputed during the parallel staging phase.

#define L_CHUNK 32
#define W_WARM  16
#define CPB     64                            // chunks (threads) per block
#define SPAN    (CPB * L_CHUNK + W_WARM)      // 2064 steps per block
#define NGRP    (SPAN / 4)                    // 516 float4 groups
#define NSTEP   (W_WARM + L_CHUNK)            // 48 steps per thread
#define NROWS   (CPB + 1)                     // 65 span rows of 32
#define PITCH   33                            // odd pitch

__global__ void __launch_bounds__(CPB, 8)
ricker_kernel(const float* __restrict__ N0,
              const float* __restrict__ Temp,
              const float* __restrict__ sigma,
              const float* __restrict__ eps,
              const float* __restrict__ mp,
              float* __restrict__ out,
              int S)   // S = T-1 steps
{
    __shared__ float2 sK[NROWS][PITCH];       // (K0, K1) per step
    __shared__ float  sE[NROWS][PITCH];       // e per step
    __shared__ float  sOut[CPB][PITCH];       // live outputs (64 x 32)

    const int tid    = threadIdx.x;
    const int chunk0 = blockIdx.x * CPB;
    const int base   = chunk0 * L_CHUNK - W_WARM;  // global step of span[0]

    const float alpha = mp[0];
    const float beta  = mp[1];
    const float bx    = mp[2];
    const float cx    = mp[3];
    const float sg    = sigma[0];
    const float n0v   = N0[0];

    const float abx = alpha * bx;
    const float acx = alpha * cx;
    const float c   = alpha * beta;
    const float K2  = 0.5f * c * c;           // constant cubic coefficient

    if (chunk0 == 0 && tid == 0) out[0] = n0v;

    // ---- stage the span: coalesced float4 loads, compute (K0,K1,e), STS ----
#pragma unroll
    for (int j = 0; j < 9; ++j) {
        const int p = tid + CPB * j;          // float4 group id
        if (p < NGRP) {
            const int i = 4 * p;              // span entry
            const int g = base + i;           // global step index
            float4 t4, e4;
            if (g >= 0 && g + 4 <= S) {
                t4 = *reinterpret_cast<const float4*>(Temp + g);
                e4 = *reinterpret_cast<const float4*>(eps  + g);
            } else {
                float tv[4], ev[4];
#pragma unroll
                for (int u = 0; u < 4; ++u) {
                    int gi = g + u;
                    gi = gi < 0 ? 0 : (gi > S - 1 ? S - 1 : gi);
                    tv[u] = Temp[gi];
                    ev[u] = eps[gi];
                }
                t4 = make_float4(tv[0], tv[1], tv[2], tv[3]);
                e4 = make_float4(ev[0], ev[1], ev[2], ev[3]);
            }
            const int r = i >> 5, s0 = i & 31;   // 4 entries stay in one row
            float tv4[4] = {t4.x, t4.y, t4.z, t4.w};
            float ev4[4] = {e4.x, e4.y, e4.z, e4.w};
#pragma unroll
            for (int u = 0; u < 4; ++u) {
                const float a  = fmaf(tv4[u], fmaf(tv4[u], acx, abx), alpha); // alpha*(1+f)
                const float K0 = fmaf(a, fmaf(a, 0.5f, 1.0f), 1.0f);          // 1+a+a^2/2
                const float K1 = fmaf(-c, a, -c);                             // -c(1+a)
                sK[r][s0 + u] = make_float2(K0, K1);
                sE[r][s0 + u] = sg * ev4[u];
            }
        }
    }
    __syncthreads();

    // ---- serial 48-step chain (16 warm + 32 live): 8 cycles/step ----
    const bool isC0 = (chunk0 + tid == 0);
    float n = 1.0f;                           // warm-up seed
#pragma unroll
    for (int s = 0; s < NSTEP; ++s) {
        if (s == W_WARM && isC0) n = n0v;     // chunk 0: exact start
        const int rr = (s < L_CHUNK) ? tid : tid + 1;       // compile-time per s
        const int ss = (s < L_CHUNK) ? s   : s - L_CHUNK;
        const float2 k = sK[rr][ss];
        const float  e = sE[rr][ss];
        const float t1 = fmaf(K2,  n, k.y);   // K2*n + K1
        const float n2 = n * n;
        const float u  = fmaf(k.x, n, e);     // K0*n + e
        n              = fmaf(t1, n2, u);     // K2 n^3 + K1 n^2 + K0 n + e
        if (s >= W_WARM) sOut[tid][s - W_WARM] = n;
    }
    __syncthreads();

    // ---- coalesced output: out[chunk0*32 + e + 1] for e in [0, 2048) ----
    const int qbase = chunk0 * L_CHUNK;
#pragma unroll
    for (int j = 0; j < L_CHUNK; ++j) {
        const int e2  = tid + CPB * j;        // 0..2047
        const int idx = qbase + e2;           // global step index
        if (idx < S)
            out[idx + 1] = sOut[e2 >> 5][e2 & 31];
    }
}

extern "C" void kernel_launch(void* const* d_in, const int* in_sizes, int n_in,
                              void* d_out, int out_size) {
    const float* N0    = (const float*)d_in[0];
    const float* Temp  = (const float*)d_in[1];
    const float* sigma = (const float*)d_in[2];
    const float* eps   = (const float*)d_in[3];
    const float* mp    = (const float*)d_in[4];
    float* out = (float*)d_out;

    const int T = in_sizes[1];
    const int S = T - 1;
    const int C = (S + L_CHUNK - 1) / L_CHUNK;        // 131072
    const int blocks = (C + CPB - 1) / CPB;           // 2048

    ricker_kernel<<<blocks, CPB>>>(N0, Temp, sigma, eps, mp, out, S);
}

// round 8
// speedup vs baseline: 1.2900x; 1.2900x over previous
#include <cuda_runtime.h>

// Ricker scan, chunk-parallel via contraction warm-up (round 8).
//   n_{i+1} = n_i * exp(alpha*(1 - beta*n_i + f_i)) + sigma*eps_i
// R5 skeleton (L=32, W=16, CPB=64, single 2064-step span staged once) with
// ONE change: no separate sOut. Chain outputs live in 32 registers, then the
// sIn buffer is reused for output staging after a barrier. smem/CTA drops
// 25.6KB -> 17.2KB, lifting the smem occupancy cap from 8 to 13 CTAs/SM.

#define L_CHUNK 32
#define W_WARM  16
#define CPB     64                            // chunks (threads) per block
#define SPAN    (CPB * L_CHUNK + W_WARM)      // 2064 steps per block
#define NGRP    (SPAN / 4)                    // 516 float4 groups
#define NSTEP   (W_WARM + L_CHUNK)            // 48 steps per thread
#define NROWS   (CPB + 1)                     // 65 span rows of 32
#define PITCH   33                            // odd pitch: conflict-free

__global__ void __launch_bounds__(CPB)
ricker_kernel(const float* __restrict__ N0,
              const float* __restrict__ Temp,
              const float* __restrict__ sigma,
              const float* __restrict__ eps,
              const float* __restrict__ mp,
              float* __restrict__ out,
              int S)   // S = T-1 steps
{
    // span entry i at sIn[i>>5][i&31]; reused as float[64][33] for outputs
    __shared__ float2 sIn[NROWS][PITCH];      // 17.2 KB

    const int tid    = threadIdx.x;
    const int chunk0 = blockIdx.x * CPB;
    const int base   = chunk0 * L_CHUNK - W_WARM;  // global step of span[0]

    const float alpha = mp[0];
    const float beta  = mp[1];
    const float bx    = mp[2];
    const float cx    = mp[3];
    const float sg    = sigma[0];
    const float n0v   = N0[0];

    const float abx = alpha * bx;
    const float acx = alpha * cx;
    const float bc  = -alpha * beta;

    if (chunk0 == 0 && tid == 0) out[0] = n0v;

    // ---- stage the span: coalesced float4 loads, compute (a, e), STS ----
#pragma unroll
    for (int j = 0; j < 9; ++j) {
        const int p = tid + CPB * j;          // float4 group id
        if (p < NGRP) {
            const int i = 4 * p;              // span entry
            const int g = base + i;           // global step index
            float4 t4, e4;
            if (g >= 0 && g + 4 <= S) {
                t4 = *reinterpret_cast<const float4*>(Temp + g);
                e4 = *reinterpret_cast<const float4*>(eps  + g);
            } else {
                float tv[4], ev[4];
#pragma unroll
                for (int u = 0; u < 4; ++u) {
                    int gi = g + u;
                    gi = gi < 0 ? 0 : (gi > S - 1 ? S - 1 : gi);
                    tv[u] = Temp[gi];
                    ev[u] = eps[gi];
                }
                t4 = make_float4(tv[0], tv[1], tv[2], tv[3]);
                e4 = make_float4(ev[0], ev[1], ev[2], ev[3]);
            }
            // i & 31 <= 28, so all 4 entries stay in one row
            float2* rp = &sIn[i >> 5][i & 31];
            rp[0] = make_float2(fmaf(t4.x, fmaf(t4.x, acx, abx), alpha), sg * e4.x);
            rp[1] = make_float2(fmaf(t4.y, fmaf(t4.y, acx, abx), alpha), sg * e4.y);
            rp[2] = make_float2(fmaf(t4.z, fmaf(t4.z, acx, abx), alpha), sg * e4.z);
            rp[3] = make_float2(fmaf(t4.w, fmaf(t4.w, acx, abx), alpha), sg * e4.w);
        }
    }
    __syncthreads();

    // ---- serial 48-step chain (16 warm + 32 live), outputs to registers ----
    const bool isC0 = (chunk0 + tid == 0);
    float ro[L_CHUNK];
    float n = 1.0f;                           // warm-up seed
#pragma unroll
    for (int s = 0; s < NSTEP; ++s) {
        if (s == W_WARM && isC0) n = n0v;     // chunk 0: exact start
        const float2 ae = (s < L_CHUNK) ? sIn[tid][s] : sIn[tid + 1][s - L_CHUNK];
        const float x = fmaf(bc, n, ae.x);    // alpha*(1 - beta*n + f)
        float p       = fmaf(x, 0.16666667f, 0.5f);
        p             = fmaf(x, p, 1.0f);
        p             = fmaf(x, p, 1.0f);     // ~exp(x), deg-3 Taylor
        n             = fmaf(n, p, ae.y);
        if (s >= W_WARM) ro[s - W_WARM] = n;
    }
    __syncthreads();                          // all chain reads of sIn done

    // ---- stage outputs into the REUSED buffer, then coalesced STG ----
    float* sO = reinterpret_cast<float*>(sIn);   // [CPB][PITCH] floats
#pragma unroll
    for (int s = 0; s < L_CHUNK; ++s)
        sO[tid * PITCH + s] = ro[s];          // banks (tid+s)%32: conflict-free
    __syncthreads();

    const int qbase = chunk0 * L_CHUNK;
#pragma unroll
    for (int j = 0; j < L_CHUNK; ++j) {
        const int e2  = tid + CPB * j;        // 0..2047
        const int idx = qbase + e2;           // global step index
        if (idx < S)
            out[idx + 1] = sO[(e2 >> 5) * PITCH + (e2 & 31)];
    }
}

extern "C" void kernel_launch(void* const* d_in, const int* in_sizes, int n_in,
                              void* d_out, int out_size) {
    const float* N0    = (const float*)d_in[0];
    const float* Temp  = (const float*)d_in[1];
    const float* sigma = (const float*)d_in[2];
    const float* eps   = (const float*)d_in[3];
    const float* mp    = (const float*)d_in[4];
    float* out = (float*)d_out;

    const int T = in_sizes[1];
    const int S = T - 1;
    const int C = (S + L_CHUNK - 1) / L_CHUNK;        // 131072
    const int blocks = (C + CPB - 1) / CPB;           // 2048

    ricker_kernel<<<blocks, CPB>>>(N0, Temp, sigma, eps, mp, out, S);
}

// round 9
// speedup vs baseline: 1.2928x; 1.0022x over previous
#include <cuda_runtime.h>

// Ricker scan, chunk-parallel via contraction warm-up (round 9).
//   n_{i+1} = n_i * exp(alpha*(1 - beta*n_i + f_i)) + sigma*eps_i
// Chunk c produces out[c*32 .. c*32+31] (states n_{c*32..c*32+31}):
// 16 warm steps + 32 live steps, inputs at global steps c*32-17+s.
// Outputs: exactly T floats, aligned -> unguarded STG.128.
// Chain: deg-2 exp Taylor, 4 FMA, 16-cycle dependence per step.

#define L_CHUNK 32
#define W_WARM  16
#define CPB     64                            // chunks (threads) per block
#define NSTEP   (W_WARM + L_CHUNK)            // 48 steps per thread
#define SPANE   2068                          // padded span entries (aligned)
#define NGRP    517                           // float4 groups (2068/4)
#define NROWS   65                            // span rows of 32
#define PITCH   33                            // odd pitch

__global__ void __launch_bounds__(CPB, 13)
ricker_kernel(const float* __restrict__ N0,
              const float* __restrict__ Temp,
              const float* __restrict__ sigma,
              const float* __restrict__ eps,
              const float* __restrict__ mp,
              float* __restrict__ out,
              int S, int nBlocks)   // S = T-1 steps
{
    // span entry i at sIn[i>>5][i&31]; reused as float[64][PITCH] for outputs
    __shared__ float2 sIn[NROWS][PITCH];      // 17.2 KB

    const int tid    = threadIdx.x;
    const int chunk0 = blockIdx.x * CPB;
    // span pos 0 <-> global step alignedBase (== chunk0*32 - 20, 4-aligned)
    const int aBase  = chunk0 * L_CHUNK - 20;

    const float alpha = mp[0];
    const float beta  = mp[1];
    const float bx    = mp[2];
    const float cx    = mp[3];
    const float sg    = sigma[0];
    const float n0v   = N0[0];

    const float abx = alpha * bx;
    const float acx = alpha * cx;
    const float bc  = -alpha * beta;

    const bool edge = (blockIdx.x == 0) || (blockIdx.x == nBlocks - 1);

    // ---- stage the span: coalesced float4 loads, compute (a, e), STS ----
#pragma unroll
    for (int j = 0; j < 9; ++j) {
        const int p = tid + CPB * j;          // float4 group id
        if (p < NGRP) {
            const int i = 4 * p;              // span entry
            const int g = aBase + i;          // global step index (4-aligned)
            float4 t4, e4;
            if (!edge || (g >= 0 && g + 4 <= S)) {
                t4 = *reinterpret_cast<const float4*>(Temp + g);
                e4 = *reinterpret_cast<const float4*>(eps  + g);
            } else {
                float tv[4], ev[4];
#pragma unroll
                for (int u = 0; u < 4; ++u) {
                    int gi = g + u;
                    gi = gi < 0 ? 0 : (gi > S - 1 ? S - 1 : gi);
                    tv[u] = Temp[gi];
                    ev[u] = eps[gi];
                }
                t4 = make_float4(tv[0], tv[1], tv[2], tv[3]);
                e4 = make_float4(ev[0], ev[1], ev[2], ev[3]);
            }
            // i & 31 <= 28, so all 4 entries stay in one row
            float2* rp = &sIn[i >> 5][i & 31];
            rp[0] = make_float2(fmaf(t4.x, fmaf(t4.x, acx, abx), alpha), sg * e4.x);
            rp[1] = make_float2(fmaf(t4.y, fmaf(t4.y, acx, abx), alpha), sg * e4.y);
            rp[2] = make_float2(fmaf(t4.z, fmaf(t4.z, acx, abx), alpha), sg * e4.z);
            rp[3] = make_float2(fmaf(t4.w, fmaf(t4.w, acx, abx), alpha), sg * e4.w);
        }
    }
    __syncthreads();

    // ---- serial 48-step chain; step s uses span pos 32*tid + 3 + s ----
    const bool isC0 = (chunk0 + tid == 0);
    float ro[L_CHUNK];
    float n = 1.0f;                           // warm-up seed
#pragma unroll
    for (int s = 0; s < NSTEP; ++s) {
        if (s == W_WARM + 1 && isC0) n = n0v; // chunk 0: exact n_0 before step g=0
        const int pos = 3 + s;                // offset within thread's window
        const float2 ae = (pos < 32) ? sIn[tid][pos] : sIn[tid + 1][pos - 32];
        const float x = fmaf(bc, n, ae.x);    // alpha*(1 - beta*n + f)
        const float p = fmaf(x, fmaf(x, 0.5f, 1.0f), 1.0f);  // ~exp(x), deg-2
        n             = fmaf(n, p, ae.y);
        if (s >= W_WARM) ro[s - W_WARM] = n;  // ro[u] = n_{c*32+u}
    }
    if (isC0) ro[0] = n0v;                    // out[0] = N0 (not a step result)
    __syncthreads();                          // all chain reads of sIn done

    // ---- stage outputs into REUSED buffer (pitch 33, conflict-free) ----
    float* sO = reinterpret_cast<float*>(sIn);
#pragma unroll
    for (int s = 0; s < L_CHUNK; ++s)
        sO[tid * PITCH + s] = ro[s];
    __syncthreads();

    // ---- vectorized output: 512 float4 groups, fully aligned, no guards ----
    float4* out4 = reinterpret_cast<float4*>(out) + chunk0 * (L_CHUNK / 4);
#pragma unroll
    for (int j = 0; j < 8; ++j) {
        const int q = tid + CPB * j;          // 0..511
        const int r = q >> 3;                 // source row
        const int c = 4 * (q & 7);            // source col
        const float* sp = &sO[r * PITCH + c];
        out4[q] = make_float4(sp[0], sp[1], sp[2], sp[3]);
    }
}

extern "C" void kernel_launch(void* const* d_in, const int* in_sizes, int n_in,
                              void* d_out, int out_size) {
    const float* N0    = (const float*)d_in[0];
    const float* Temp  = (const float*)d_in[1];
    const float* sigma = (const float*)d_in[2];
    const float* eps   = (const float*)d_in[3];
    const float* mp    = (const float*)d_in[4];
    float* out = (float*)d_out;

    const int T = in_sizes[1];                // 4194304
    const int S = T - 1;
    const int C = (T + L_CHUNK - 1) / L_CHUNK;        // 131072 chunks (exact)
    const int blocks = (C + CPB - 1) / CPB;           // 2048

    ricker_kernel<<<blocks, CPB>>>(N0, Temp, sigma, eps, mp, out, S, blocks);
}

// round 10
// speedup vs baseline: 1.3274x; 1.0267x over previous
#include <cuda_runtime.h>

// Ricker scan, chunk-parallel via contraction warm-up (round 10: pipelined).
//   n_{i+1} = n_i * exp(alpha*(1 - beta*n_i + f_i)) + sigma*eps_i
// Each block processes TWO 64-chunk spans (A = 2*bid, B = 2*bid+1).
// Span B's raw LDGs are issued into registers BEFORE chain A runs, hiding
// DRAM latency under the serial chain. Grid = 1024 = exactly one wave at
// 7 CTAs/SM (no partial-wave tail). Deg-2 exp chain, aligned STG.128 out.

#define L_CHUNK 32
#define W_WARM  16
#define CPB     64                            // chunks (threads) per span
#define NSTEP   (W_WARM + L_CHUNK)            // 48 steps per thread
#define NGRP    517                           // float4 groups per span (2068/4)
#define NROWS   65                            // span rows of 32
#define PITCH   33                            // odd pitch: conflict-free

__global__ void __launch_bounds__(CPB, 7)
ricker_kernel(const float* __restrict__ N0,
              const float* __restrict__ Temp,
              const float* __restrict__ sigma,
              const float* __restrict__ eps,
              const float* __restrict__ mp,
              float* __restrict__ out,
              int S, int nSpans)   // S = T-1 steps
{
    __shared__ float2 sIn[NROWS][PITCH];      // 17.2 KB input span
    __shared__ float  sOut[CPB][PITCH];       //  8.4 KB output staging

    const int tid   = threadIdx.x;
    const int spanA = blockIdx.x * 2;
    const int spanB = spanA + 1;

    const float alpha = mp[0];
    const float beta  = mp[1];
    const float bx    = mp[2];
    const float cx    = mp[3];
    const float sg    = sigma[0];
    const float n0v   = N0[0];

    const float abx = alpha * bx;
    const float acx = alpha * cx;
    const float bc  = -alpha * beta;

    // ---- raw span load (coalesced float4; clamped only on edge spans) ----
    auto ldg_span = [&](int span, bool edge, float4* rT, float4* rE) {
#pragma unroll
        for (int j = 0; j < 9; ++j) {
            const int p = tid + CPB * j;
            if (p < NGRP) {
                const int g = span * 2048 - 20 + 4 * p;   // 4-aligned
                if (!edge || (g >= 0 && g + 4 <= S)) {
                    rT[j] = *reinterpret_cast<const float4*>(Temp + g);
                    rE[j] = *reinterpret_cast<const float4*>(eps  + g);
                } else {
                    float tv[4], ev[4];
#pragma unroll
                    for (int u = 0; u < 4; ++u) {
                        int gi = g + u;
                        gi = gi < 0 ? 0 : (gi > S - 1 ? S - 1 : gi);
                        tv[u] = Temp[gi];
                        ev[u] = eps[gi];
                    }
                    rT[j] = make_float4(tv[0], tv[1], tv[2], tv[3]);
                    rE[j] = make_float4(ev[0], ev[1], ev[2], ev[3]);
                }
            }
        }
    };

    // ---- compute (a, e) and store a span into sIn ----
    auto stage_span = [&](const float4* rT, const float4* rE) {
#pragma unroll
        for (int j = 0; j < 9; ++j) {
            const int p = tid + CPB * j;
            if (p < NGRP) {
                const int i = 4 * p;                      // i&31 <= 28: one row
                float2* rp = &sIn[i >> 5][i & 31];
                rp[0] = make_float2(fmaf(rT[j].x, fmaf(rT[j].x, acx, abx), alpha), sg * rE[j].x);
                rp[1] = make_float2(fmaf(rT[j].y, fmaf(rT[j].y, acx, abx), alpha), sg * rE[j].y);
                rp[2] = make_float2(fmaf(rT[j].z, fmaf(rT[j].z, acx, abx), alpha), sg * rE[j].z);
                rp[3] = make_float2(fmaf(rT[j].w, fmaf(rT[j].w, acx, abx), alpha), sg * rE[j].w);
            }
        }
    };

    // ---- serial 48-step chain; step s reads span pos 32*tid + 3 + s ----
    auto chain = [&](int span, float* ro) {
        const bool isC0 = (span == 0 && tid == 0);
        float n = 1.0f;
#pragma unroll
        for (int s = 0; s < NSTEP; ++s) {
            if (s == W_WARM + 1 && isC0) n = n0v;   // exact n_0 before step g=0
            const int pos = 3 + s;
            const float2 ae = (pos < 32) ? sIn[tid][pos] : sIn[tid + 1][pos - 32];
            const float x = fmaf(bc, n, ae.x);                    // a - c*n
            const float p = fmaf(x, fmaf(x, 0.5f, 1.0f), 1.0f);   // ~exp(x)
            n             = fmaf(n, p, ae.y);
            if (s >= W_WARM) ro[s - W_WARM] = n;
        }
        if (isC0) ro[0] = n0v;                       // out[0] = N0
    };

    auto sts_out = [&](const float* ro) {
#pragma unroll
        for (int s = 0; s < L_CHUNK; ++s)
            sOut[tid][s] = ro[s];                    // banks (tid+s)%32
    };

    auto stg_out = [&](int span) {
        float4* out4 = reinterpret_cast<float4*>(out) + span * 512;
#pragma unroll
        for (int j = 0; j < 8; ++j) {
            const int q = tid + CPB * j;             // 0..511
            const float* sp = &sOut[q >> 3][4 * (q & 7)];
            out4[q] = make_float4(sp[0], sp[1], sp[2], sp[3]);
        }
    };

    const bool edgeA = (spanA == 0);
    const bool edgeB = (spanB == nSpans - 1);

    float4 rT[9], rE[9];
    float  ro[L_CHUNK];

    // phase 1: stage span A
    ldg_span(spanA, edgeA, rT, rE);
    stage_span(rT, rE);
    __syncthreads();

    // phase 2: prefetch span B's raw data, then chain A (hides B's DRAM lat)
    ldg_span(spanB, edgeB, rT, rE);
    chain(spanA, ro);
    __syncthreads();                                 // chain-A sIn reads done

    // phase 3: stage span B into sIn; stage A outputs into sOut
    stage_span(rT, rE);
    sts_out(ro);
    __syncthreads();

    // phase 4: write span-A outputs while running chain B
    stg_out(spanA);
    chain(spanB, ro);
    __syncthreads();                                 // STG-A sOut reads done

    // phase 5: stage + write span-B outputs
    sts_out(ro);
    __syncthreads();
    stg_out(spanB);
}

extern "C" void kernel_launch(void* const* d_in, const int* in_sizes, int n_in,
                              void* d_out, int out_size) {
    const float* N0    = (const float*)d_in[0];
    const float* Temp  = (const float*)d_in[1];
    const float* sigma = (const float*)d_in[2];
    const float* eps   = (const float*)d_in[3];
    const float* mp    = (const float*)d_in[4];
    float* out = (float*)d_out;

    const int T = in_sizes[1];                // 4194304
    const int S = T - 1;
    const int C = (T + L_CHUNK - 1) / L_CHUNK;        // 131072 chunks
    const int nSpans = (C + CPB - 1) / CPB;           // 2048 spans
    const int blocks = nSpans / 2;                    // 1024 (single wave)

    ricker_kernel<<<blocks, CPB>>>(N0, Temp, sigma, eps, mp, out, S, nSpans);
}

// round 11
// speedup vs baseline: 1.5282x; 1.1513x over previous
#include <cuda_runtime.h>
#include <cstdint>

// Ricker scan, chunk-parallel via contraction warm-up (round 11: cp.async).
//   n_{i+1} = n_i * exp(alpha*(1 - beta*n_i + f_i)) + sigma*eps_i
// Chunk length 31 (stride 31 = -1 mod 32 -> conflict-free LDS from a
// CONTIGUOUS smem buffer), warm-up 13. Raw Temp/eps pulled into smem with
// cp.async.cg (no register landing, L1 bypass, background drain). Forcing
// math (a = alpha*(1+f), sg*e) folded into the chain off the critical path.
// 3 spans per block, rolling 2-buffer pipeline, grid = one full wave.

#define LC     31                             // live steps per chunk
#define W_WARM 13                             // warm-up steps
#define NSTEP  (W_WARM + LC)                  // 44 steps per thread
#define CPB    64                             // chunks (threads) per block
#define OPS    (CPB * LC)                     // 1984 outputs per span
#define ENT    2000                           // staged entries per span
#define NG4    (ENT / 4)                      // 500 float4 per stream
#define NS     3                              // spans per block

__device__ __forceinline__ void cp16(float* dst_smem, const float* src) {
    uint32_t d = (uint32_t)__cvta_generic_to_shared(dst_smem);
    asm volatile("cp.async.cg.shared.global [%0], [%1], 16;" :: "r"(d), "l"(src));
}
__device__ __forceinline__ void cp_commit() {
    asm volatile("cp.async.commit_group;");
}
template <int N> __device__ __forceinline__ void cp_wait() {
    asm volatile("cp.async.wait_group %0;" :: "n"(N));
}

__global__ void __launch_bounds__(CPB)
ricker_kernel(const float* __restrict__ N0,
              const float* __restrict__ Temp,
              const float* __restrict__ sigma,
              const float* __restrict__ eps,
              const float* __restrict__ mp,
              float* __restrict__ out,
              int S, int nSpans, int outQ)   // S = T-1; outQ = T/4
{
    __shared__ float sT[2][ENT];              // raw Temp spans (ping-pong)
    __shared__ float sE[2][ENT];              // raw eps spans
    __shared__ float sOut[OPS];               // output staging (1984 floats)

    const int tid = threadIdx.x;

    const float alpha = mp[0];
    const float beta  = mp[1];
    const float bx    = mp[2];
    const float cx    = mp[3];
    const float sg    = sigma[0];
    const float n0v   = N0[0];

    const float abx = alpha * bx;
    const float acx = alpha * cx;
    const float bc  = -alpha * beta;

    const int s0 = blockIdx.x * NS;

    // ---- stage a span's raw inputs into smem buf (cp.async fast path) ----
    auto stage = [&](int span, int b) {
        if (span >= nSpans) return;
        const long aB = (long)span * OPS - 16;          // 4-aligned entry base
        const bool edge = (aB < 0) || (aB + ENT > (long)S);
        float* bT = sT[b];
        float* bE = sE[b];
        if (!edge) {
#pragma unroll
            for (int j = 0; j < 8; ++j) {
                const int q = tid + CPB * j;
                if (q < NG4) {
                    cp16(bT + 4 * q, Temp + aB + 4 * q);
                    cp16(bE + 4 * q, eps  + aB + 4 * q);
                }
            }
        } else {                                        // rare: first/last span
#pragma unroll
            for (int j = 0; j < 8; ++j) {
                const int q = tid + CPB * j;
                if (q < NG4) {
#pragma unroll
                    for (int u = 0; u < 4; ++u) {
                        long gi = aB + 4 * q + u;
                        gi = gi < 0 ? 0 : (gi > S - 1 ? S - 1 : gi);
                        bT[4 * q + u] = Temp[gi];
                        bE[4 * q + u] = eps[gi];
                    }
                }
            }
        }
    };

    // ---- 44-step serial chain; step s reads span pos 31*tid + 2 + s ----
    // pos stride 31 across lanes => bank (2+s-lane) mod 32: conflict-free.
    auto chain = [&](int span, int b, float* ro) {
        if (span >= nSpans) return;
        const float* bT = sT[b];
        const float* bE = sE[b];
        const int  base = LC * tid + 2;
        const bool isC0 = (span == 0 && tid == 0);
        float n = 1.0f;
#pragma unroll
        for (int s = 0; s < NSTEP; ++s) {
            if (s == W_WARM + 1 && isC0) n = n0v;       // exact n_0 before i=0
            const float t = bT[base + s];
            const float e = bE[base + s];
            const float a = fmaf(t, fmaf(t, acx, abx), alpha);   // off-chain
            const float x = fmaf(bc, n, a);                      // chain
            const float p = fmaf(x, fmaf(x, 0.5f, 1.0f), 1.0f);  // ~exp(x)
            n             = fmaf(n, p, sg * e);
            if (s >= W_WARM) ro[s - W_WARM] = n;        // ro[u] = n_{o0+u}
        }
        if (isC0) ro[0] = n0v;                          // out[0] = N0
    };

    auto sts_out = [&](int span, const float* ro) {
        if (span >= nSpans) return;
#pragma unroll
        for (int k = 0; k < LC; ++k)
            sOut[LC * tid + k] = ro[k];                 // stride 31: no conflicts
    };

    auto stg_out = [&](int span) {
        if (span >= nSpans) return;
        float4* o4 = reinterpret_cast<float4*>(out);
        const int gb = span * (OPS / 4);                // 496 float4 per span
#pragma unroll
        for (int j = 0; j < 8; ++j) {
            const int q = tid + CPB * j;
            if (q < OPS / 4 && gb + q < outQ) {
                const float* sp = &sOut[4 * q];
                o4[gb + q] = make_float4(sp[0], sp[1], sp[2], sp[3]);
            }
        }
    };

    float ro[LC];

    // prologue: spans s0, s0+1 in flight
    stage(s0,     0); cp_commit();
    stage(s0 + 1, 1); cp_commit();

    // ---- span 0 of 3 ----
    cp_wait<1>(); __syncthreads();                      // buf0 ready
    chain(s0, 0, ro);
    __syncthreads();                                    // buf0 reads done
    stage(s0 + 2, 0); cp_commit();                      // refill buf0
    sts_out(s0, ro); __syncthreads();
    stg_out(s0);

    // ---- span 1 of 3 ----
    cp_wait<1>(); __syncthreads();                      // buf1 ready; sOut free
    chain(s0 + 1, 1, ro);
    __syncthreads();
    sts_out(s0 + 1, ro); __syncthreads();
    stg_out(s0 + 1);

    // ---- span 2 of 3 ----
    cp_wait<0>(); __syncthreads();                      // buf0 ready; sOut free
    chain(s0 + 2, 0, ro);
    __syncthreads();
    sts_out(s0 + 2, ro); __syncthreads();
    stg_out(s0 + 2);
}

extern "C" void kernel_launch(void* const* d_in, const int* in_sizes, int n_in,
                              void* d_out, int out_size) {
    const float* N0    = (const float*)d_in[0];
    const float* Temp  = (const float*)d_in[1];
    const float* sigma = (const float*)d_in[2];
    const float* eps   = (const float*)d_in[3];
    const float* mp    = (const float*)d_in[4];
    float* out = (float*)d_out;

    const int T = in_sizes[1];                          // 4194304
    const int S = T - 1;
    const int nSpans = (T + OPS - 1) / OPS;             // 2115
    const int blocks = (nSpans + NS - 1) / NS;          // 705 (one wave @5/SM)
    const int outQ   = T / 4;

    ricker_kernel<<<blocks, CPB>>>(N0, Temp, sigma, eps, mp, out,
                                   S, nSpans, outQ);
}

// round 12
// speedup vs baseline: 1.5851x; 1.0372x over previous
#include <cuda_runtime.h>
#include <cstdint>

// Ricker scan, chunk-parallel via contraction warm-up (round 12).
//   n_{i+1} = n_i * exp(alpha*(1 - beta*n_i + f_i)) + sigma*eps_i
// R11 engine (LC=31 conflict-free contiguous smem, cp.async.cg staging,
// deg-2 exp chain) with: NS=2 spans/block, sOut eliminated (reuse drained
// input buffer), regs capped via launch_bounds(64,7) -> 7 CTAs/SM (smem 32KB),
// and span-A STG overlapped with span-B chain.

#define LC     31                             // live steps per chunk
#define W_WARM 13                             // warm-up steps
#define NSTEP  (W_WARM + LC)                  // 44 steps per thread
#define CPB    64                             // chunks (threads) per block
#define OPS    (CPB * LC)                     // 1984 outputs per span
#define ENT    2000                           // staged entries per span
#define NG4    (ENT / 4)                      // 500 float4 per stream

__device__ __forceinline__ void cp16(float* dst_smem, const float* src) {
    uint32_t d = (uint32_t)__cvta_generic_to_shared(dst_smem);
    asm volatile("cp.async.cg.shared.global [%0], [%1], 16;" :: "r"(d), "l"(src));
}
__device__ __forceinline__ void cp_commit() {
    asm volatile("cp.async.commit_group;");
}
template <int N> __device__ __forceinline__ void cp_wait() {
    asm volatile("cp.async.wait_group %0;" :: "n"(N));
}

__global__ void __launch_bounds__(CPB, 7)
ricker_kernel(const float* __restrict__ N0,
              const float* __restrict__ Temp,
              const float* __restrict__ sigma,
              const float* __restrict__ eps,
              const float* __restrict__ mp,
              float* __restrict__ out,
              int S, int nSpans, int outQ)   // S = T-1; outQ = T/4
{
    __shared__ float sT[2][ENT];              // raw Temp spans (ping-pong)
    __shared__ float sE[2][ENT];              // raw eps spans

    const int tid = threadIdx.x;

    const float alpha = mp[0];
    const float beta  = mp[1];
    const float bx    = mp[2];
    const float cx    = mp[3];
    const float sg    = sigma[0];
    const float n0v   = N0[0];

    const float abx = alpha * bx;
    const float acx = alpha * cx;
    const float bc  = -alpha * beta;

    const int s0 = blockIdx.x * 2;

    // ---- stage a span's raw inputs into smem buf (cp.async fast path) ----
    auto stage = [&](int span, int b) {
        if (span >= nSpans) return;
        const long aB = (long)span * OPS - 16;          // 4-aligned entry base
        const bool edge = (aB < 0) || (aB + ENT > (long)S);
        float* bT = sT[b];
        float* bE = sE[b];
        if (!edge) {
#pragma unroll
            for (int j = 0; j < 8; ++j) {
                const int q = tid + CPB * j;
                if (q < NG4) {
                    cp16(bT + 4 * q, Temp + aB + 4 * q);
                    cp16(bE + 4 * q, eps  + aB + 4 * q);
                }
            }
        } else {                                        // rare: first/last span
#pragma unroll
            for (int j = 0; j < 8; ++j) {
                const int q = tid + CPB * j;
                if (q < NG4) {
#pragma unroll
                    for (int u = 0; u < 4; ++u) {
                        long gi = aB + 4 * q + u;
                        gi = gi < 0 ? 0 : (gi > S - 1 ? S - 1 : gi);
                        bT[4 * q + u] = Temp[gi];
                        bE[4 * q + u] = eps[gi];
                    }
                }
            }
        }
    };

    // ---- 44-step serial chain; step s reads span pos 31*tid + 2 + s ----
    // pos stride 31 across lanes => bank (2+s-lane) mod 32: conflict-free.
    auto chain = [&](int span, int b, float* ro) {
        if (span >= nSpans) return;
        const float* bT = sT[b];
        const float* bE = sE[b];
        const int  base = LC * tid + 2;
        const bool isC0 = (span == 0 && tid == 0);
        float n = 1.0f;
#pragma unroll
        for (int s = 0; s < NSTEP; ++s) {
            if (s == W_WARM + 1 && isC0) n = n0v;       // exact n_0 before i=0
            const float t = bT[base + s];
            const float e = bE[base + s];
            const float a = fmaf(t, fmaf(t, acx, abx), alpha);   // off-chain
            const float x = fmaf(bc, n, a);                      // chain
            const float p = fmaf(x, fmaf(x, 0.5f, 1.0f), 1.0f);  // ~exp(x)
            n             = fmaf(n, p, sg * e);
            if (s >= W_WARM) ro[s - W_WARM] = n;        // ro[u] = n_{o0+u}
        }
        if (isC0) ro[0] = n0v;                          // out[0] = N0
    };

    float* sO = sT[0];                                  // reuse drained buf0

    auto sts_out = [&](int span, const float* ro) {
        if (span >= nSpans) return;
#pragma unroll
        for (int k = 0; k < LC; ++k)
            sO[LC * tid + k] = ro[k];                   // stride 31: no conflicts
    };

    auto stg_out = [&](int span) {
        if (span >= nSpans) return;
        float4* o4 = reinterpret_cast<float4*>(out);
        const int gb = span * (OPS / 4);                // 496 float4 per span
#pragma unroll
        for (int j = 0; j < 8; ++j) {
            const int q = tid + CPB * j;
            if (q < OPS / 4 && gb + q < outQ) {
                const float* sp = &sO[4 * q];
                o4[gb + q] = make_float4(sp[0], sp[1], sp[2], sp[3]);
            }
        }
    };

    float ro[LC];

    // prologue: both spans' staging in flight immediately
    stage(s0,     0); cp_commit();
    stage(s0 + 1, 1); cp_commit();

    // ---- span A ----
    cp_wait<1>(); __syncthreads();                      // buf0 ready
    chain(s0, 0, ro);
    __syncthreads();                                    // buf0 chain reads done
    sts_out(s0, ro);
    cp_wait<0>();                                       // buf1 ready (no-op by now)
    __syncthreads();                                    // sOut(=buf0) visible
    stg_out(s0);                                        // fire-and-forget STG...
    chain(s0 + 1, 1, ro);                               // ...hidden under chain B
    __syncthreads();                                    // stg-A smem reads done

    // ---- span B ----
    sts_out(s0 + 1, ro);
    __syncthreads();
    stg_out(s0 + 1);
}

extern "C" void kernel_launch(void* const* d_in, const int* in_sizes, int n_in,
                              void* d_out, int out_size) {
    const float* N0    = (const float*)d_in[0];
    const float* Temp  = (const float*)d_in[1];
    const float* sigma = (const float*)d_in[2];
    const float* eps   = (const float*)d_in[3];
    const float* mp    = (const float*)d_in[4];
    float* out = (float*)d_out;

    const int T = in_sizes[1];                          // 4194304
    const int S = T - 1;
    const int nSpans = (T + OPS - 1) / OPS;             // 2115
    const int blocks = (nSpans + 1) / 2;                // 1058 (~one wave @7/SM)
    const int outQ   = T / 4;

    ricker_kernel<<<blocks, CPB>>>(N0, Temp, sigma, eps, mp, out,
                                   S, nSpans, outQ);
}